// round 11
// baseline (speedup 1.0000x reference)
#include <cuda_runtime.h>
#include <cuda_bf16.h>

// PairwiseDistances: d[e] = || R[idx_i[e]] - R[idx_j[e]] ||_2
// R: [N,3] f32 (N=100000); idx: int32 [E]; out: f32 [E]. E = 6,400,000.
//
// Evidence through R9: gather kernel sits at the L1tex wavefront floor
// (2 random-gather wavefronts/edge -> ~50.4us @ ~0.95 wf/cyc/SM). The only
// recoverable time is the ~3.6us pad-prologue launch. R10 fuses the pad
// into the main kernel via a grid-internal spin barrier (pad blocks are
// wave-1 resident; counters self-reset for graph replays).

#define R4_CAP 131072  // padded table capacity (2 MB); N=100000 fits

__device__ float4 g_R4[R4_CAP];
__device__ int    g_pad_done;   // zero-init; reset by last block each run
__device__ int    g_done_ctr;   // zero-init; reset by last block each run

// One LDG.128 per gather: 1 L1tex wavefront + 1 L2 sector.
__device__ __forceinline__ float4 ldg_row(int idx)
{
    float4 v;
    const float4* p = g_R4 + (unsigned)idx;
    asm("ld.global.nc.L1::evict_last.v4.f32 {%0,%1,%2,%3}, [%4];"
        : "=f"(v.x), "=f"(v.y), "=f"(v.z), "=f"(v.w)
        : "l"(p));
    return v;
}

__global__ __launch_bounds__(256) void pairwise_dist_fused_kernel(
    const int*    __restrict__ idx_i,
    const int*    __restrict__ idx_j,
    float*        __restrict__ out,
    int num_quads,                 // E/4
    const float4* __restrict__ R4in,
    int n_groups,                  // ceil(n_atoms/4)
    int n_atoms,
    int pad_blocks)                // ceil(n_groups/256); << wave-1 size
{
    // ---- Phase 1: first pad_blocks blocks build the padded table ----
    if (blockIdx.x < (unsigned)pad_blocks) {
        int g = blockIdx.x * blockDim.x + threadIdx.x;
        if (g < n_groups) {
            int base = g * 4;
            if (base + 4 <= n_atoms) {
                float4 p0 = __ldg(R4in + 3*g + 0);   // x0 y0 z0 x1
                float4 p1 = __ldg(R4in + 3*g + 1);   // y1 z1 x2 y2
                float4 p2 = __ldg(R4in + 3*g + 2);   // z2 x3 y3 z3
                g_R4[base + 0] = make_float4(p0.x, p0.y, p0.z, 0.f);
                g_R4[base + 1] = make_float4(p0.w, p1.x, p1.y, 0.f);
                g_R4[base + 2] = make_float4(p1.z, p1.w, p2.x, 0.f);
                g_R4[base + 3] = make_float4(p2.y, p2.z, p2.w, 0.f);
            } else {
                const float* r = (const float*)R4in;
                for (int a = base; a < n_atoms; ++a)
                    g_R4[a] = make_float4(r[3*a+0], r[3*a+1], r[3*a+2], 0.f);
            }
        }
        __threadfence();           // table writes visible before signal
        __syncthreads();
        if (threadIdx.x == 0) atomicAdd(&g_pad_done, 1);
    }

    // ---- Grid-internal wait: all blocks need the full table ----
    if (threadIdx.x == 0) {
        while (*(volatile int*)&g_pad_done < pad_blocks) __nanosleep(64);
        __threadfence();           // acquire: table reads after signal
    }
    __syncthreads();

    // ---- Phase 2: gather + compute (wavefront-floor kernel) ----
    int t = blockIdx.x * blockDim.x + threadIdx.x;
    if (t < num_quads) {
        int4 i4 = __ldg(reinterpret_cast<const int4*>(idx_i) + t);
        int4 j4 = __ldg(reinterpret_cast<const int4*>(idx_j) + t);

        float4 a0 = ldg_row(i4.x);
        float4 a1 = ldg_row(i4.y);
        float4 a2 = ldg_row(i4.z);
        float4 a3 = ldg_row(i4.w);
        float4 b0 = ldg_row(j4.x);
        float4 b1 = ldg_row(j4.y);
        float4 b2 = ldg_row(j4.z);
        float4 b3 = ldg_row(j4.w);

        float dx0 = a0.x-b0.x, dy0 = a0.y-b0.y, dz0 = a0.z-b0.z;
        float dx1 = a1.x-b1.x, dy1 = a1.y-b1.y, dz1 = a1.z-b1.z;
        float dx2 = a2.x-b2.x, dy2 = a2.y-b2.y, dz2 = a2.z-b2.z;
        float dx3 = a3.x-b3.x, dy3 = a3.y-b3.y, dz3 = a3.z-b3.z;

        float4 o;
        o.x = sqrtf(fmaf(dx0, dx0, fmaf(dy0, dy0, dz0*dz0)));
        o.y = sqrtf(fmaf(dx1, dx1, fmaf(dy1, dy1, dz1*dz1)));
        o.z = sqrtf(fmaf(dx2, dx2, fmaf(dy2, dy2, dz2*dz2)));
        o.w = sqrtf(fmaf(dx3, dx3, fmaf(dy3, dy3, dz3*dz3)));

        reinterpret_cast<float4*>(out)[t] = o;
    }

    // ---- Epilogue: last finishing block resets counters for the next
    // graph replay (globals are zero-init for the very first launch). ----
    __syncthreads();
    if (threadIdx.x == 0) {
        __threadfence();
        int n = atomicAdd(&g_done_ctr, 1);
        if (n == (int)gridDim.x - 1) {
            g_pad_done = 0;
            g_done_ctr = 0;
            __threadfence();
        }
    }
}

// ---------- fallback: direct scalar gathers if N exceeds scratch ----------
__global__ __launch_bounds__(256) void pairwise_dist_direct_kernel(
    const float* __restrict__ R,
    const int*   __restrict__ idx_i,
    const int*   __restrict__ idx_j,
    float* __restrict__ out,
    int E)
{
    int e = blockIdx.x * blockDim.x + threadIdx.x;
    if (e >= E) return;
    int i = idx_i[e], j = idx_j[e];
    float dx = R[3*(size_t)i+0] - R[3*(size_t)j+0];
    float dy = R[3*(size_t)i+1] - R[3*(size_t)j+1];
    float dz = R[3*(size_t)i+2] - R[3*(size_t)j+2];
    out[e] = sqrtf(fmaf(dx, dx, fmaf(dy, dy, dz*dz)));
}

// ---------- scalar tail for E % 4 != 0 (defensive; reads padded table) ----
__global__ void pairwise_dist_tail_kernel(
    const int* __restrict__ idx_i,
    const int* __restrict__ idx_j,
    float* __restrict__ out,
    int start, int E)
{
    int e = start + blockIdx.x * blockDim.x + threadIdx.x;
    if (e >= E) return;
    float4 a = g_R4[(unsigned)idx_i[e]];
    float4 b = g_R4[(unsigned)idx_j[e]];
    float dx = a.x-b.x, dy = a.y-b.y, dz = a.z-b.z;
    out[e] = sqrtf(fmaf(dx, dx, fmaf(dy, dy, dz*dz)));
}

extern "C" void kernel_launch(void* const* d_in, const int* in_sizes, int n_in,
                              void* d_out, int out_size)
{
    const float* R     = (const float*)d_in[0];
    const int*   idx_i = (const int*)d_in[1];
    const int*   idx_j = (const int*)d_in[2];
    float*       out   = (float*)d_out;

    int n_atoms = in_sizes[0] / 3;
    int E = in_sizes[1];

    if (n_atoms > R4_CAP) {
        int blocks = (E + 255) / 256;
        pairwise_dist_direct_kernel<<<blocks, 256>>>(R, idx_i, idx_j, out, E);
        return;
    }

    int num_quads  = E >> 2;
    int n_groups   = (n_atoms + 3) / 4;
    int pad_blocks = (n_groups + 255) / 256;   // 98 for N=100000

    int blocks = (num_quads + 255) / 256;      // 6250 for E=6.4M
    if (blocks < pad_blocks) blocks = pad_blocks;  // ensure all pad work runs

    pairwise_dist_fused_kernel<<<blocks, 256>>>(
        idx_i, idx_j, out, num_quads,
        (const float4*)R, n_groups, n_atoms, pad_blocks);

    int tail = E & 3;
    if (tail)
        pairwise_dist_tail_kernel<<<1, 32>>>(idx_i, idx_j, out, E - tail, E);
}

// round 14
// speedup vs baseline: 1.1903x; 1.1903x over previous
#include <cuda_runtime.h>
#include <cuda_bf16.h>

// PairwiseDistances: d[e] = || R[idx_i[e]] - R[idx_j[e]] ||_2
// R: [N,3] f32 (N=100000); idx: int32 [E]; out: f32 [E]. E = 6,400,000.
//
// Evidence: gather kernel is at the L1tex wavefront floor (~50.4us).
// R11 fusion regressed (per-CTA __threadfence -> CCTL.IVALL L1 flush killed
// evict_last residency). R12/R13: two kernels, overlapped with PDL —
// main kernel prefetches indices, then cudaGridDependencySynchronize()
// (HW wait, no L1 flush, no atomics) before touching the padded table.

#define R4_CAP 131072  // padded table capacity (2 MB); N=100000 fits

__device__ float4 g_R4[R4_CAP];

// ---------- prologue: pad R[N,3] -> g_R4[N] (float4), vectorized ----------
__global__ __launch_bounds__(256) void pad_R_kernel(
    const float4* __restrict__ R4in, int n_groups, int n_atoms)
{
#if __CUDA_ARCH__ >= 900
    // Let the dependent (main) kernel begin launching immediately; its
    // cudaGridDependencySynchronize() still waits for our completion.
    cudaTriggerProgrammaticLaunchCompletion();
#endif
    int g = blockIdx.x * blockDim.x + threadIdx.x;
    if (g >= n_groups) return;
    int base = g * 4;
    if (base + 4 <= n_atoms) {
        float4 p0 = __ldg(R4in + 3*g + 0);   // x0 y0 z0 x1
        float4 p1 = __ldg(R4in + 3*g + 1);   // y1 z1 x2 y2
        float4 p2 = __ldg(R4in + 3*g + 2);   // z2 x3 y3 z3
        g_R4[base + 0] = make_float4(p0.x, p0.y, p0.z, 0.f);
        g_R4[base + 1] = make_float4(p0.w, p1.x, p1.y, 0.f);
        g_R4[base + 2] = make_float4(p1.z, p1.w, p2.x, 0.f);
        g_R4[base + 3] = make_float4(p2.y, p2.z, p2.w, 0.f);
    } else {
        const float* r = (const float*)R4in;
        for (int a = base; a < n_atoms; ++a)
            g_R4[a] = make_float4(r[3*a+0], r[3*a+1], r[3*a+2], 0.f);
    }
}

// One LDG.128 per gather: 1 L1tex wavefront + 1 L2 sector.
__device__ __forceinline__ float4 ldg_row(int idx)
{
    float4 v;
    const float4* p = g_R4 + (unsigned)idx;
    asm("ld.global.nc.L1::evict_last.v4.f32 {%0,%1,%2,%3}, [%4];"
        : "=f"(v.x), "=f"(v.y), "=f"(v.z), "=f"(v.w)
        : "l"(p));
    return v;
}

// ---------- main kernel (wavefront floor) with PDL dependency wait --------
__global__ __launch_bounds__(256) void pairwise_dist_kernel(
    const int*   __restrict__ idx_i,
    const int*   __restrict__ idx_j,
    float* __restrict__ out,
    int num_quads)   // E/4
{
    int t = blockIdx.x * blockDim.x + threadIdx.x;
    bool active = (t < num_quads);

    // Prefetch index vectors — independent of the padded table, so this
    // overlaps the pad kernel's execution.
    int4 i4 = make_int4(0,0,0,0), j4 = make_int4(0,0,0,0);
    if (active) {
        i4 = __ldg(reinterpret_cast<const int4*>(idx_i) + t);
        j4 = __ldg(reinterpret_cast<const int4*>(idx_j) + t);
    }

#if __CUDA_ARCH__ >= 900
    // HW wait for pad_R_kernel completion + memory visibility.
    cudaGridDependencySynchronize();
#endif

    if (!active) return;

    float4 a0 = ldg_row(i4.x);
    float4 a1 = ldg_row(i4.y);
    float4 a2 = ldg_row(i4.z);
    float4 a3 = ldg_row(i4.w);
    float4 b0 = ldg_row(j4.x);
    float4 b1 = ldg_row(j4.y);
    float4 b2 = ldg_row(j4.z);
    float4 b3 = ldg_row(j4.w);

    float dx0 = a0.x-b0.x, dy0 = a0.y-b0.y, dz0 = a0.z-b0.z;
    float dx1 = a1.x-b1.x, dy1 = a1.y-b1.y, dz1 = a1.z-b1.z;
    float dx2 = a2.x-b2.x, dy2 = a2.y-b2.y, dz2 = a2.z-b2.z;
    float dx3 = a3.x-b3.x, dy3 = a3.y-b3.y, dz3 = a3.z-b3.z;

    float4 o;
    o.x = sqrtf(fmaf(dx0, dx0, fmaf(dy0, dy0, dz0*dz0)));
    o.y = sqrtf(fmaf(dx1, dx1, fmaf(dy1, dy1, dz1*dz1)));
    o.z = sqrtf(fmaf(dx2, dx2, fmaf(dy2, dy2, dz2*dz2)));
    o.w = sqrtf(fmaf(dx3, dx3, fmaf(dy3, dy3, dz3*dz3)));

    reinterpret_cast<float4*>(out)[t] = o;
}

// ---------- fallback: direct scalar gathers if N exceeds scratch ----------
__global__ __launch_bounds__(256) void pairwise_dist_direct_kernel(
    const float* __restrict__ R,
    const int*   __restrict__ idx_i,
    const int*   __restrict__ idx_j,
    float* __restrict__ out,
    int E)
{
    int e = blockIdx.x * blockDim.x + threadIdx.x;
    if (e >= E) return;
    int i = idx_i[e], j = idx_j[e];
    float dx = R[3*(size_t)i+0] - R[3*(size_t)j+0];
    float dy = R[3*(size_t)i+1] - R[3*(size_t)j+1];
    float dz = R[3*(size_t)i+2] - R[3*(size_t)j+2];
    out[e] = sqrtf(fmaf(dx, dx, fmaf(dy, dy, dz*dz)));
}

// ---------- scalar tail for E % 4 != 0 (defensive) ----------
__global__ void pairwise_dist_tail_kernel(
    const int* __restrict__ idx_i,
    const int* __restrict__ idx_j,
    float* __restrict__ out,
    int start, int E)
{
    int e = start + blockIdx.x * blockDim.x + threadIdx.x;
    if (e >= E) return;
    float4 a = g_R4[(unsigned)idx_i[e]];
    float4 b = g_R4[(unsigned)idx_j[e]];
    float dx = a.x-b.x, dy = a.y-b.y, dz = a.z-b.z;
    out[e] = sqrtf(fmaf(dx, dx, fmaf(dy, dy, dz*dz)));
}

extern "C" void kernel_launch(void* const* d_in, const int* in_sizes, int n_in,
                              void* d_out, int out_size)
{
    const float* R     = (const float*)d_in[0];
    const int*   idx_i = (const int*)d_in[1];
    const int*   idx_j = (const int*)d_in[2];
    float*       out   = (float*)d_out;

    int n_atoms = in_sizes[0] / 3;
    int E = in_sizes[1];

    if (n_atoms > R4_CAP) {
        int blocks = (E + 255) / 256;
        pairwise_dist_direct_kernel<<<blocks, 256>>>(R, idx_i, idx_j, out, E);
        return;
    }

    int n_groups = (n_atoms + 3) / 4;
    pad_R_kernel<<<(n_groups + 255) / 256, 256>>>(
        (const float4*)R, n_groups, n_atoms);

    int num_quads = E >> 2;
    int blocks = (num_quads + 255) / 256;
    if (blocks > 0) {
        // Launch with PDL: may begin while pad_R_kernel is still running;
        // the in-kernel cudaGridDependencySynchronize provides ordering.
        cudaLaunchConfig_t cfg = {};
        cfg.gridDim  = dim3(blocks, 1, 1);
        cfg.blockDim = dim3(256, 1, 1);
        cfg.dynamicSmemBytes = 0;
        cfg.stream = 0;  // legacy default stream (same as <<<>>>)
        cudaLaunchAttribute attr[1];
        attr[0].id = cudaLaunchAttributeProgrammaticStreamSerialization;
        attr[0].val.programmaticStreamSerializationAllowed = 1;
        cfg.attrs = attr;
        cfg.numAttrs = 1;
        cudaLaunchKernelEx(&cfg, pairwise_dist_kernel,
                           idx_i, idx_j, out, num_quads);
    }

    int tail = E & 3;
    if (tail)
        pairwise_dist_tail_kernel<<<1, 32>>>(idx_i, idx_j, out, E - tail, E);
}